// round 3
// baseline (speedup 1.0000x reference)
#include <cuda_runtime.h>
#include <math.h>
#include <stdint.h>

#define A_N 49104
#define B_N 8
#define C_N 80
#define K_N 256
#define IMG 512.0f
#define TOTAL (B_N * A_N)      // 392832 = 64 * 6138
#define NBIN 32768
#define ROW4 20                // 80 floats = 20 float4 per anchor row

// -------- device scratch --------
__device__ float    g_scores[TOTAL];
__device__ unsigned g_hist1[B_N * NBIN];
__device__ unsigned g_hist2[B_N * NBIN];
__device__ unsigned g_T1[B_N];
__device__ unsigned g_rem1[B_N];
__device__ float4   g_topb[B_N * K_N];
__device__ float    g_tops[B_N * K_N];
__device__ int      g_topl[B_N * K_N];

// ============================================================
__global__ void zeroHist() {
    int i = blockIdx.x * blockDim.x + threadIdx.x;
    if (i < B_N * NBIN) { g_hist1[i] = 0u; g_hist2[i] = 0u; }
}

// ============================================================
// Stage A: 4 threads per anchor. Thread j of an anchor reads
// float4s j, j+4, ..., j+16 (coalesced 64B chunks per anchor),
// shfl-reduces the max, computes sigmoid score, and feeds a
// warp-aggregated global histogram on the top-15 score bits.
// ============================================================
__global__ __launch_bounds__(256) void stageA(const float* __restrict__ cls) {
    int tid = threadIdx.x;
    int g = blockIdx.x * 64 + (tid >> 2);           // anchor (global, incl. batch)
    int j = tid & 3;

    const float4* row = reinterpret_cast<const float4*>(cls) + (size_t)g * ROW4 + j;
    float m = -INFINITY;
#pragma unroll
    for (int i = 0; i < 5; i++) {
        float4 v = row[i * 4];
        m = fmaxf(m, fmaxf(fmaxf(v.x, v.y), fmaxf(v.z, v.w)));
    }
    m = fmaxf(m, __shfl_xor_sync(0xffffffffu, m, 1));
    m = fmaxf(m, __shfl_xor_sync(0xffffffffu, m, 2));

    float score = 1.0f / (1.0f + expf(-m));
    if (!(score > 0.01f)) score = 0.0f;

    int b = g / A_N;
    unsigned key = ((unsigned)b << 15) | (__float_as_uint(score) >> 15);

    unsigned peers = __match_any_sync(0xffffffffu, key);
    int leader = __ffs(peers) - 1;
    if (j == 0) g_scores[g] = score;
    if ((tid & 31) == leader)
        atomicAdd(&g_hist1[key], (unsigned)(__popc(peers) >> 2));
}

// ============================================================
// suffix-select: find bin (from top) where cumulative count
// crosses `target`. 32768 bins, 1024 threads.
// ============================================================
__device__ void suffix_select(const unsigned* __restrict__ h, unsigned target,
                              unsigned* csum, unsigned* ws,
                              unsigned* out_bin, unsigned* out_rem) {
    int tid = threadIdx.x;
    unsigned s = 0;
#pragma unroll 8
    for (int i = 0; i < 32; i++) s += h[tid * 32 + i];
    csum[tid] = s;
    __syncthreads();
    if (tid < 32) {
        unsigned t = 0;
#pragma unroll 8
        for (int i = 0; i < 32; i++) t += csum[tid * 32 + i];
        ws[tid] = t;
    }
    __syncthreads();
    if (tid == 0) {
        unsigned cum = 0;
        int w = 31;
        for (; w > 0; w--) { if (cum + ws[w] >= target) break; cum += ws[w]; }
        int c = w * 32 + 31;
        for (; c > w * 32; c--) { if (cum + csum[c] >= target) break; cum += csum[c]; }
        int bbin = c * 32 + 31;
        for (; bbin > c * 32; bbin--) { if (cum + h[bbin] >= target) break; cum += h[bbin]; }
        *out_bin = (unsigned)bbin;
        *out_rem = target - cum;
    }
    __syncthreads();
}

__global__ __launch_bounds__(1024) void select1() {
    __shared__ unsigned csum[1024], ws[32], obin, orem;
    int b = blockIdx.x;
    suffix_select(g_hist1 + b * NBIN, K_N, csum, ws, &obin, &orem);
    if (threadIdx.x == 0) { g_T1[b] = obin; g_rem1[b] = orem; }
}

// ============================================================
__global__ void hist2k() {
    int g = blockIdx.x * blockDim.x + threadIdx.x;
    if (g >= TOTAL) return;
    int b = g / A_N;
    unsigned k = __float_as_uint(g_scores[g]);
    if ((k >> 15) == g_T1[b])
        atomicAdd(&g_hist2[b * NBIN + (k & 0x7FFFu)], 1u);
}

// ============================================================
// Collect: exact threshold (pass 2), gather >T plus lowest-index
// ==T, bitonic sort 256 by (score desc, index asc), then
// recompute label (4-thread argmax) + decode box for winners.
// ============================================================
__global__ __launch_bounds__(1024) void collect(const float* __restrict__ cls,
                                                const float* __restrict__ regs,
                                                const float* __restrict__ anchors) {
    int b = blockIdx.x;
    int tid = threadIdx.x;
    int lane = tid & 31, wid = tid >> 5;

    __shared__ unsigned csum[1024], ws[32];
    __shared__ unsigned sh_bin, sh_need;
    suffix_select(g_hist2 + b * NBIN, g_rem1[b], csum, ws, &sh_bin, &sh_need);

    __shared__ unsigned sh_T;
    __shared__ unsigned long long top[K_N];
    __shared__ unsigned gt_cnt;
    if (tid == 0) {
        sh_T = (g_T1[b] << 15) | sh_bin;
        gt_cnt = 0;
    }
    __syncthreads();
    unsigned T = sh_T;
    unsigned need = sh_need;
    unsigned G = K_N - need;

    const float* sc = g_scores + b * A_N;
    for (int a = tid; a < A_N; a += 1024) {
        unsigned k = __float_as_uint(sc[a]);
        if (k > T) {
            unsigned p = atomicAdd(&gt_cnt, 1u);
            top[p] = (((unsigned long long)k) << 32) | (0xFFFFFFFFu - (unsigned)a);
        }
    }
    __syncthreads();

    // ordered compaction of ==T (ascending index, early exit)
    __shared__ unsigned eqidx[K_N];
    __shared__ unsigned wq[32];
    __shared__ unsigned eqc;
    if (tid == 0) eqc = 0;
    __syncthreads();
    for (int base = 0; base < A_N; base += 1024) {
        int a = base + tid;
        bool pred = (a < A_N) && (__float_as_uint(sc[a]) == T);
        unsigned m = __ballot_sync(0xffffffffu, pred);
        if (lane == 0) wq[wid] = __popc(m);
        __syncthreads();
        if (tid == 0) {
            unsigned cb = eqc;
#pragma unroll
            for (int w = 0; w < 32; w++) { unsigned c = wq[w]; wq[w] = cb; cb += c; }
            eqc = cb;
        }
        __syncthreads();
        if (pred) {
            unsigned pos = wq[wid] + __popc(m & ((1u << lane) - 1u));
            if (pos < need) eqidx[pos] = (unsigned)a;
        }
        __syncthreads();
        if (eqc >= need) break;
    }
    if (tid < need)
        top[G + tid] = (((unsigned long long)T) << 32) | (0xFFFFFFFFu - eqidx[tid]);
    __syncthreads();

    // bitonic sort 256 descending by (score bits, ~index)
    for (unsigned kk = 2; kk <= K_N; kk <<= 1) {
        for (unsigned j = kk >> 1; j > 0; j >>= 1) {
            if (tid < K_N) {
                unsigned ixj = tid ^ j;
                if (ixj > (unsigned)tid) {
                    unsigned long long x = top[tid], y = top[ixj];
                    bool descseg = ((tid & kk) == 0);
                    bool doswap = descseg ? (x < y) : (x > y);
                    if (doswap) { top[tid] = y; top[ixj] = x; }
                }
            }
            __syncthreads();
        }
    }

    // gather: 4 threads per winner recompute argmax; lane j==0 decodes box
    int e = tid >> 2, j = tid & 3;
    unsigned long long v = top[e];
    unsigned k = (unsigned)(v >> 32);
    unsigned a = 0xFFFFFFFFu - (unsigned)(v & 0xFFFFFFFFu);
    const float4* row = reinterpret_cast<const float4*>(cls) +
                        ((size_t)b * A_N + a) * ROW4;
    float m = -INFINITY;
    int arg = 0;
#pragma unroll
    for (int q0 = 0; q0 < 5; q0++) {
        int q = j + 4 * q0;
        float4 x = row[q];
        int c = 4 * q;
        if (x.x > m) { m = x.x; arg = c; }
        if (x.y > m) { m = x.y; arg = c + 1; }
        if (x.z > m) { m = x.z; arg = c + 2; }
        if (x.w > m) { m = x.w; arg = c + 3; }
    }
#pragma unroll
    for (int off = 1; off < 4; off <<= 1) {
        float mo = __shfl_xor_sync(0xffffffffu, m, off);
        int ao = __shfl_xor_sync(0xffffffffu, arg, off);
        if (mo > m || (mo == m && ao < arg)) { m = mo; arg = ao; }
    }
    if (j == 0) {
        int o = b * K_N + e;
        g_tops[o] = __uint_as_float(k);
        g_topl[o] = arg;
        float4 an = reinterpret_cast<const float4*>(anchors)[a];
        float aw = an.z - an.x, ah = an.w - an.y;
        float acx = an.x + 0.5f * aw, acy = an.y + 0.5f * ah;
        float4 rg = reinterpret_cast<const float4*>(regs)[(size_t)b * A_N + a];
        float cx = acx + rg.x * aw;
        float cy = acy + rg.y * ah;
        float dw = fminf(fmaxf(rg.z, -4.0f), 4.0f);
        float dh = fminf(fmaxf(rg.w, -4.0f), 4.0f);
        float w = aw * expf(dw);
        float h = ah * expf(dh);
        float x1 = fminf(fmaxf(cx - 0.5f * w, 0.0f), IMG);
        float y1 = fminf(fmaxf(cy - 0.5f * h, 0.0f), IMG);
        float x2 = fminf(fmaxf(cx + 0.5f * w, 0.0f), IMG);
        float y2 = fminf(fmaxf(cy + 0.5f * h, 0.0f), IMG);
        g_topb[o] = make_float4(x1, y1, x2, y2);
    }
}

// ============================================================
// Stage C: sequential NMS on 256 sorted candidates + output
// ============================================================
__global__ __launch_bounds__(K_N) void stageC(float* __restrict__ out, int out_size) {
    int b = blockIdx.x;
    int tid = threadIdx.x;

    __shared__ float4 bx[K_N];
    __shared__ float sc[K_N];
    __shared__ unsigned msk[K_N][8];
    __shared__ unsigned keepw[8];

    bx[tid] = g_topb[b * K_N + tid];
    sc[tid] = g_tops[b * K_N + tid];
    __syncthreads();

    float4 me = bx[tid];
    float myarea = fmaxf(me.z - me.x, 0.0f) * fmaxf(me.w - me.y, 0.0f);
    unsigned words[8] = {0u, 0u, 0u, 0u, 0u, 0u, 0u, 0u};
#pragma unroll 4
    for (int j = 0; j < K_N; j++) {
        float4 o = bx[j];
        float ix1 = fmaxf(me.x, o.x);
        float iy1 = fmaxf(me.y, o.y);
        float ix2 = fminf(me.z, o.z);
        float iy2 = fminf(me.w, o.w);
        float iw = fmaxf(ix2 - ix1, 0.0f);
        float ih = fmaxf(iy2 - iy1, 0.0f);
        float inter = iw * ih;
        float oarea = fmaxf(o.z - o.x, 0.0f) * fmaxf(o.w - o.y, 0.0f);
        float uni = myarea + oarea - inter;
        float iou = inter / fmaxf(uni, 1e-8f);
        if (iou > 0.5f) words[j >> 5] |= 1u << (j & 31);
    }
#pragma unroll
    for (int w = 0; w < 8; w++) msk[tid][w] = words[w];
    __syncthreads();

    if (tid == 0) {
#pragma unroll
        for (int w = 0; w < 8; w++) keepw[w] = 0u;
        for (int i = 0; i < K_N; i++) {
            bool k0 = sc[i] > 0.0f;
            unsigned sup = 0u;
            int wi = i >> 5;
            for (int w = 0; w < wi; w++) sup |= msk[i][w] & keepw[w];
            unsigned below = (1u << (i & 31)) - 1u;
            sup |= msk[i][wi] & keepw[wi] & below;
            if (k0 && sup == 0u) keepw[wi] |= 1u << (i & 31);
        }
    }
    __syncthreads();

    bool kp = (keepw[tid >> 5] >> (tid & 31)) & 1u;
    float kf = kp ? 1.0f : 0.0f;
    int base = b * K_N + tid;

    out[base * 5 + 0] = me.x * kf;
    out[base * 5 + 1] = me.y * kf;
    out[base * 5 + 2] = me.z * kf;
    out[base * 5 + 3] = me.w * kf;
    out[base * 5 + 4] = sc[tid] * kf;
    if (out_size >= B_N * K_N * 5 + B_N * K_N)
        out[B_N * K_N * 5 + base] = (float)g_topl[base];
    if (out_size >= B_N * K_N * 5 + 2 * B_N * K_N)
        out[B_N * K_N * 5 + B_N * K_N + base] = kf;
}

// ============================================================
extern "C" void kernel_launch(void* const* d_in, const int* in_sizes, int n_in,
                              void* d_out, int out_size) {
    const float* cls = nullptr;
    const float* regs = nullptr;
    const float* anchors = nullptr;
    for (int i = 0; i < n_in; i++) {
        if (in_sizes[i] == B_N * A_N * C_N) cls = (const float*)d_in[i];
        else if (in_sizes[i] == B_N * A_N * 4) regs = (const float*)d_in[i];
        else if (in_sizes[i] == A_N * 4) anchors = (const float*)d_in[i];
    }
    if (!cls || !regs || !anchors) return;

    float* out = (float*)d_out;

    zeroHist<<<(B_N * NBIN + 1023) / 1024, 1024>>>();
    stageA<<<TOTAL / 64, 256>>>(cls);
    select1<<<B_N, 1024>>>();
    hist2k<<<(TOTAL + 1023) / 1024, 1024>>>();
    collect<<<B_N, 1024>>>(cls, regs, anchors);
    stageC<<<B_N, K_N>>>(out, out_size);
}

// round 4
// speedup vs baseline: 1.3862x; 1.3862x over previous
#include <cuda_runtime.h>
#include <math.h>
#include <stdint.h>

#define A_N 49104
#define B_N 8
#define C_N 80
#define K_N 256
#define IMG 512.0f
#define ROW4 20                 // 80 floats = 20 float4 per anchor
#define CH 2048                 // anchors per chunk
#define NCH 24                  // chunks per batch (24*2048 >= 49104)
#define NLIST 32                // padded list count for merge (pow2 >= NCH)

typedef unsigned long long u64;

// -------- device scratch --------
__device__ u64 g_cand[B_N * NCH * K_N];   // 49152 keys

// ============================================================
// K1: fused score + local top-256 per 2048-anchor chunk.
//   4 threads per anchor read float4s j, j+4, ..., j+16,
//   shfl-reduce max, sigmoid+threshold, key = score|~idx,
//   bitonic sort 2048 desc in smem, emit top 256.
// ============================================================
__global__ __launch_bounds__(512) void k_topk_local(const float* __restrict__ cls) {
    __shared__ u64 sk[CH];
    const int tid = threadIdx.x;
    const int b = blockIdx.x / NCH;
    const int c = blockIdx.x % NCH;
    const int base = c * CH;
    const float4* cls4 = reinterpret_cast<const float4*>(cls) + (size_t)b * A_N * ROW4;

#pragma unroll
    for (int it = 0; it < (CH * 4) / 512; it++) {
        int task = it * 512 + tid;
        int al = task >> 2;
        int j = task & 3;
        int a = base + al;
        float m = -INFINITY;
        if (a < A_N) {
            const float4* row = cls4 + (size_t)a * ROW4 + j;
#pragma unroll
            for (int i = 0; i < 5; i++) {
                float4 v = row[i * 4];
                m = fmaxf(m, fmaxf(fmaxf(v.x, v.y), fmaxf(v.z, v.w)));
            }
        }
        m = fmaxf(m, __shfl_xor_sync(0xffffffffu, m, 1));
        m = fmaxf(m, __shfl_xor_sync(0xffffffffu, m, 2));
        if (j == 0) {
            u64 key = 0ull;
            if (a < A_N) {
                float score = 1.0f / (1.0f + expf(-m));
                if (!(score > 0.01f)) score = 0.0f;
                key = ((u64)__float_as_uint(score) << 32) |
                      (u64)(0xFFFFFFFFu - (unsigned)a);
            }
            sk[al] = key;
        }
    }
    __syncthreads();

    // bitonic sort 2048 descending
    for (unsigned k = 2; k <= CH; k <<= 1) {
        for (unsigned j = k >> 1; j > 0; j >>= 1) {
#pragma unroll
            for (int q = 0; q < CH / 512; q++) {
                int e = q * 512 + tid;
                int f = e ^ (int)j;
                if (f > e) {
                    u64 x = sk[e], y = sk[f];
                    bool desc = ((e & k) == 0);
                    if (desc ? (x < y) : (x > y)) { sk[e] = y; sk[f] = x; }
                }
            }
            __syncthreads();
        }
    }

    if (tid < K_N)
        g_cand[blockIdx.x * K_N + tid] = sk[tid];
}

// ============================================================
// K2: per-batch merge (bitonic top-k tree) + gather/decode + NMS + output.
// ============================================================
extern __shared__ unsigned char sh_raw[];

__global__ __launch_bounds__(1024) void k_merge_nms(const float* __restrict__ cls,
                                                    const float* __restrict__ regs,
                                                    const float* __restrict__ anchors,
                                                    float* __restrict__ out,
                                                    int out_size) {
    const int b = blockIdx.x;
    const int tid = threadIdx.x;

    u64*      keys = reinterpret_cast<u64*>(sh_raw);                       // 8192 * 8B
    float4*   bx   = reinterpret_cast<float4*>(sh_raw + 65536);            // 256 * 16B
    float*    sc   = reinterpret_cast<float*>(sh_raw + 65536 + 4096);      // 256 * 4B
    int*      lb   = reinterpret_cast<int*>(sh_raw + 65536 + 5120);        // 256 * 4B
    unsigned* msk  = reinterpret_cast<unsigned*>(sh_raw + 65536 + 6144);   // 256*8 * 4B
    __shared__ unsigned keepw[8];

    // load candidates (24 lists), pad to 32 lists with zero keys
    for (int i = tid; i < NLIST * K_N; i += 1024)
        keys[i] = (i < NCH * K_N) ? g_cand[b * NCH * K_N + i] : 0ull;
    __syncthreads();

    // merge tree: 5 levels; at level l, pair lists (stride 256<<l)
#pragma unroll
    for (int lvl = 0; lvl < 5; lvl++) {
        int npair = (NLIST / 2) >> lvl;
        // phase 1: keep top-256 of each pair -> bitonic sequence in A slot
        for (int t = tid; t < npair * K_N; t += 1024) {
            int p = t >> 8, i = t & 255;
            int baseA = p * (512 << lvl);
            int baseB = baseA + (256 << lvl);
            u64 x = keys[baseA + i];
            u64 y = keys[baseB + 255 - i];
            keys[baseA + i] = (x > y) ? x : y;
        }
        __syncthreads();
        // phase 2: bitonic clean (descending) of each surviving 256-list
        for (int j = 128; j >= 1; j >>= 1) {
            for (int t = tid; t < npair * 128; t += 1024) {
                int p = t / 128, r = t % 128;
                int seg = p * (512 << lvl);
                int e = seg + ((r / j) * 2 * j) + (r % j);
                int f = e + j;
                u64 x = keys[e], y = keys[f];
                if (x < y) { keys[e] = y; keys[f] = x; }
            }
            __syncthreads();
        }
    }
    // keys[0..255] = exact top-256, sorted (score desc, idx asc)

    // gather: 4 threads per winner recompute argmax; j==0 decodes box
    {
        int e = tid >> 2, j = tid & 3;
        u64 v = keys[e];
        unsigned kbits = (unsigned)(v >> 32);
        unsigned a = 0xFFFFFFFFu - (unsigned)(v & 0xFFFFFFFFu);
        const float4* row = reinterpret_cast<const float4*>(cls) +
                            ((size_t)b * A_N + a) * ROW4;
        float m = -INFINITY;
        int arg = 0;
#pragma unroll
        for (int q0 = 0; q0 < 5; q0++) {
            int q = j + 4 * q0;
            float4 x = row[q];
            int cc = 4 * q;
            if (x.x > m) { m = x.x; arg = cc; }
            if (x.y > m) { m = x.y; arg = cc + 1; }
            if (x.z > m) { m = x.z; arg = cc + 2; }
            if (x.w > m) { m = x.w; arg = cc + 3; }
        }
#pragma unroll
        for (int off = 1; off < 4; off <<= 1) {
            float mo = __shfl_xor_sync(0xffffffffu, m, off);
            int ao = __shfl_xor_sync(0xffffffffu, arg, off);
            if (mo > m || (mo == m && ao < arg)) { m = mo; arg = ao; }
        }
        if (j == 0) {
            sc[e] = __uint_as_float(kbits);
            lb[e] = arg;
            float4 an = reinterpret_cast<const float4*>(anchors)[a];
            float aw = an.z - an.x, ah = an.w - an.y;
            float acx = an.x + 0.5f * aw, acy = an.y + 0.5f * ah;
            float4 rg = reinterpret_cast<const float4*>(regs)[(size_t)b * A_N + a];
            float cx = acx + rg.x * aw;
            float cy = acy + rg.y * ah;
            float dw = fminf(fmaxf(rg.z, -4.0f), 4.0f);
            float dh = fminf(fmaxf(rg.w, -4.0f), 4.0f);
            float w = aw * expf(dw);
            float h = ah * expf(dh);
            float x1 = fminf(fmaxf(cx - 0.5f * w, 0.0f), IMG);
            float y1 = fminf(fmaxf(cy - 0.5f * h, 0.0f), IMG);
            float x2 = fminf(fmaxf(cx + 0.5f * w, 0.0f), IMG);
            float y2 = fminf(fmaxf(cy + 0.5f * h, 0.0f), IMG);
            bx[e] = make_float4(x1, y1, x2, y2);
        }
    }
    __syncthreads();

    // NMS: per-candidate IoU>0.5 bitmasks (threads 0..255)
    if (tid < K_N) {
        float4 me = bx[tid];
        float myarea = fmaxf(me.z - me.x, 0.0f) * fmaxf(me.w - me.y, 0.0f);
        unsigned words[8] = {0u, 0u, 0u, 0u, 0u, 0u, 0u, 0u};
#pragma unroll 4
        for (int j = 0; j < K_N; j++) {
            float4 o = bx[j];
            float ix1 = fmaxf(me.x, o.x);
            float iy1 = fmaxf(me.y, o.y);
            float ix2 = fminf(me.z, o.z);
            float iy2 = fminf(me.w, o.w);
            float iw = fmaxf(ix2 - ix1, 0.0f);
            float ih = fmaxf(iy2 - iy1, 0.0f);
            float inter = iw * ih;
            float oarea = fmaxf(o.z - o.x, 0.0f) * fmaxf(o.w - o.y, 0.0f);
            float uni = myarea + oarea - inter;
            float iou = inter / fmaxf(uni, 1e-8f);
            if (iou > 0.5f) words[j >> 5] |= 1u << (j & 31);
        }
#pragma unroll
        for (int w = 0; w < 8; w++) msk[tid * 8 + w] = words[w];
    }
    __syncthreads();

    // sequential keep recurrence
    if (tid == 0) {
#pragma unroll
        for (int w = 0; w < 8; w++) keepw[w] = 0u;
        for (int i = 0; i < K_N; i++) {
            bool k0 = sc[i] > 0.0f;
            unsigned sup = 0u;
            int wi = i >> 5;
            for (int w = 0; w < wi; w++) sup |= msk[i * 8 + w] & keepw[w];
            unsigned below = (1u << (i & 31)) - 1u;
            sup |= msk[i * 8 + wi] & keepw[wi] & below;
            if (k0 && sup == 0u) keepw[wi] |= 1u << (i & 31);
        }
    }
    __syncthreads();

    // output
    if (tid < K_N) {
        bool kp = (keepw[tid >> 5] >> (tid & 31)) & 1u;
        float kf = kp ? 1.0f : 0.0f;
        int base = b * K_N + tid;
        float4 me = bx[tid];
        out[base * 5 + 0] = me.x * kf;
        out[base * 5 + 1] = me.y * kf;
        out[base * 5 + 2] = me.z * kf;
        out[base * 5 + 3] = me.w * kf;
        out[base * 5 + 4] = sc[tid] * kf;
        if (out_size >= B_N * K_N * 5 + B_N * K_N)
            out[B_N * K_N * 5 + base] = (float)lb[tid];
        if (out_size >= B_N * K_N * 5 + 2 * B_N * K_N)
            out[B_N * K_N * 5 + B_N * K_N + base] = kf;
    }
}

// ============================================================
extern "C" void kernel_launch(void* const* d_in, const int* in_sizes, int n_in,
                              void* d_out, int out_size) {
    const float* cls = nullptr;
    const float* regs = nullptr;
    const float* anchors = nullptr;
    for (int i = 0; i < n_in; i++) {
        if (in_sizes[i] == B_N * A_N * C_N) cls = (const float*)d_in[i];
        else if (in_sizes[i] == B_N * A_N * 4) regs = (const float*)d_in[i];
        else if (in_sizes[i] == A_N * 4) anchors = (const float*)d_in[i];
    }
    if (!cls || !regs || !anchors) return;

    float* out = (float*)d_out;

    // dynamic smem for K2: 8192 keys (64KB) + bx(4KB) + sc(1KB) + lb(1KB) + msk(8KB)
    const int SMEM_K2 = 65536 + 4096 + 1024 + 1024 + 8192;
    static int configured = -1;
    if (configured < 0) {
        cudaFuncSetAttribute(k_merge_nms, cudaFuncAttributeMaxDynamicSharedMemorySize, SMEM_K2);
        configured = 1;
    }

    k_topk_local<<<B_N * NCH, 512>>>(cls);
    k_merge_nms<<<B_N, 1024, SMEM_K2>>>(cls, regs, anchors, out, out_size);
}

// round 5
// speedup vs baseline: 2.9293x; 2.1131x over previous
#include <cuda_runtime.h>
#include <math.h>
#include <stdint.h>

#define A_N 49104
#define B_N 8
#define C_N 80
#define K_N 256
#define IMG 512.0f
#define ROW4 20                 // 80 floats = 20 float4 per anchor
#define CH 2048                 // anchors per chunk
#define NCH 24                  // chunks per batch (24*2048 >= 49104)
#define NLIST 32                // padded list count for K2 merge

typedef unsigned long long u64;

// -------- device scratch --------
__device__ u64 g_cand[B_N * NCH * K_N];   // 49152 keys

// ============================================================
// warp-level helpers for register bitonic sort (desc)
// ============================================================
__device__ __forceinline__ void cx_reg(u64& a, u64& b, bool desc) {
    u64 lo = (a < b) ? a : b;
    u64 hi = (a < b) ? b : a;
    a = desc ? hi : lo;
    b = desc ? lo : hi;
}
__device__ __forceinline__ u64 cx_shfl(u64 v, int j, bool desc, int lane) {
    u64 pv = __shfl_xor_sync(0xffffffffu, v, j);
    bool lower = (lane & j) == 0;
    bool keepmax = (desc == lower);
    u64 mx = (v > pv) ? v : pv;
    u64 mn = (v > pv) ? pv : v;
    return keepmax ? mx : mn;
}

// ============================================================
// K1: fused score + chunk top-256.
//   scores -> smem keys; 16 warps register-sort 128 keys each;
//   smem merge tree (keep-all then top-256 truncating merges).
// ============================================================
__global__ __launch_bounds__(512) void k_topk_local(const float* __restrict__ cls) {
    __shared__ u64 sk[CH];
    const int tid = threadIdx.x;
    const int lane = tid & 31;
    const int w = tid >> 5;                 // warp 0..15
    const int b = blockIdx.x / NCH;
    const int c = blockIdx.x % NCH;
    const int base = c * CH;
    const float4* cls4 = reinterpret_cast<const float4*>(cls) + (size_t)b * A_N * ROW4;

    // ---- scores: 4 threads per anchor ----
#pragma unroll
    for (int it = 0; it < (CH * 4) / 512; it++) {
        int task = it * 512 + tid;
        int al = task >> 2;
        int j = task & 3;
        int a = base + al;
        float m = -INFINITY;
        if (a < A_N) {
            const float4* row = cls4 + (size_t)a * ROW4 + j;
#pragma unroll
            for (int i = 0; i < 5; i++) {
                float4 v = row[i * 4];
                m = fmaxf(m, fmaxf(fmaxf(v.x, v.y), fmaxf(v.z, v.w)));
            }
        }
        m = fmaxf(m, __shfl_xor_sync(0xffffffffu, m, 1));
        m = fmaxf(m, __shfl_xor_sync(0xffffffffu, m, 2));
        if (j == 0) {
            u64 key = 0ull;
            if (a < A_N) {
                float score = 1.0f / (1.0f + expf(-m));
                if (!(score > 0.01f)) score = 0.0f;
                key = ((u64)__float_as_uint(score) << 32) |
                      (u64)(0xFFFFFFFFu - (unsigned)a);
            }
            sk[al] = key;
        }
    }
    __syncthreads();

    // ---- register bitonic sort: each warp sorts 128 keys desc ----
    u64 v[4];
#pragma unroll
    for (int r = 0; r < 4; r++) v[r] = sk[w * 128 + r * 32 + lane];

    for (int k = 2; k <= 128; k <<= 1) {
        for (int j = k >> 1; j >= 1; j >>= 1) {
            if (j >= 32) {
                int jr = j >> 5;
#pragma unroll
                for (int r = 0; r < 4; r++) {
                    if ((r & jr) == 0) {
                        bool desc = (((r * 32) & k) == 0);
                        cx_reg(v[r], v[r | jr], desc);
                    }
                }
            } else {
#pragma unroll
                for (int r = 0; r < 4; r++) {
                    bool desc = (k >= 32) ? (((r * 32) & k) == 0)
                                          : ((lane & k) == 0);
                    v[r] = cx_shfl(v[r], j, desc, lane);
                }
            }
        }
    }
#pragma unroll
    for (int r = 0; r < 4; r++) sk[w * 128 + r * 32 + lane] = v[r];
    __syncthreads();

    // ---- L1: full merge pairs of 128 -> 8 sorted lists of 256 ----
    for (int t = tid; t < 1024; t += 512) {
        int p = t >> 7, i = t & 127;
        int e = p * 256 + i, f = p * 256 + 255 - i;
        u64 x = sk[e], y = sk[f];
        if (x < y) { sk[e] = y; sk[f] = x; }
    }
    __syncthreads();
    for (int j = 64; j >= 1; j >>= 1) {
        for (int t = tid; t < 1024; t += 512) {
            int p = t >> 7, i = t & 127;
            int e = p * 256 + (((i & ~(j - 1)) << 1) | (i & (j - 1)));
            int f = e + j;
            u64 x = sk[e], y = sk[f];
            if (x < y) { sk[e] = y; sk[f] = x; }
        }
        __syncthreads();
    }

    // ---- L2-L4: truncating merges (keep top-256 of each pair) ----
    for (int lvl = 0; lvl < 3; lvl++) {
        int npair = 4 >> lvl;               // 4, 2, 1
        int stride = 512 << lvl;            // pair base spacing
        for (int t = tid; t < npair * 256; t += 512) {
            int p = t >> 8, i = t & 255;
            int A = p * stride, B = A + (stride >> 1);
            u64 x = sk[A + i], y = sk[B + 255 - i];
            if (y > x) sk[A + i] = y;
        }
        __syncthreads();
        for (int j = 128; j >= 1; j >>= 1) {
            int ncmp = npair * 128;
            for (int t = tid; t < ncmp; t += 512) {
                int p = t >> 7, i = t & 127;
                int A = p * stride;
                int e = A + (((i & ~(j - 1)) << 1) | (i & (j - 1)));
                int f = e + j;
                u64 x = sk[e], y = sk[f];
                if (x < y) { sk[e] = y; sk[f] = x; }
            }
            __syncthreads();
        }
    }

    if (tid < K_N)
        g_cand[blockIdx.x * K_N + tid] = sk[tid];
}

// ============================================================
// K2: per-batch merge + gather/decode + NMS + output.
// ============================================================
extern __shared__ unsigned char sh_raw[];

__global__ __launch_bounds__(1024) void k_merge_nms(const float* __restrict__ cls,
                                                    const float* __restrict__ regs,
                                                    const float* __restrict__ anchors,
                                                    float* __restrict__ out,
                                                    int out_size) {
    const int b = blockIdx.x;
    const int tid = threadIdx.x;

    u64*      keys = reinterpret_cast<u64*>(sh_raw);                       // 8192 * 8B
    float4*   bx   = reinterpret_cast<float4*>(sh_raw + 65536);            // 256 * 16B
    float*    sc   = reinterpret_cast<float*>(sh_raw + 65536 + 4096);      // 256 * 4B
    int*      lb   = reinterpret_cast<int*>(sh_raw + 65536 + 5120);        // 256 * 4B
    unsigned* msk  = reinterpret_cast<unsigned*>(sh_raw + 65536 + 6144);   // 256*8 * 4B
    __shared__ unsigned keepw[8];

    for (int i = tid; i < NLIST * K_N; i += 1024)
        keys[i] = (i < NCH * K_N) ? g_cand[b * NCH * K_N + i] : 0ull;
    __syncthreads();

    // merge tree: 5 levels
#pragma unroll
    for (int lvl = 0; lvl < 5; lvl++) {
        int npair = (NLIST / 2) >> lvl;
        for (int t = tid; t < npair * K_N; t += 1024) {
            int p = t >> 8, i = t & 255;
            int baseA = p * (512 << lvl);
            int baseB = baseA + (256 << lvl);
            u64 x = keys[baseA + i];
            u64 y = keys[baseB + 255 - i];
            keys[baseA + i] = (x > y) ? x : y;
        }
        __syncthreads();
        for (int j = 128; j >= 1; j >>= 1) {
            for (int t = tid; t < npair * 128; t += 1024) {
                int p = t >> 7, i = t & 127;
                int seg = p * (512 << lvl);
                int e = seg + (((i & ~(j - 1)) << 1) | (i & (j - 1)));
                int f = e + j;
                u64 x = keys[e], y = keys[f];
                if (x < y) { keys[e] = y; keys[f] = x; }
            }
            __syncthreads();
        }
    }
    // keys[0..255] = exact top-256 (score desc, idx asc)

    // gather: 4 threads per winner recompute argmax; j==0 decodes box
    {
        int e = tid >> 2, j = tid & 3;
        u64 v = keys[e];
        unsigned kbits = (unsigned)(v >> 32);
        unsigned a = 0xFFFFFFFFu - (unsigned)(v & 0xFFFFFFFFu);
        const float4* row = reinterpret_cast<const float4*>(cls) +
                            ((size_t)b * A_N + a) * ROW4;
        float m = -INFINITY;
        int arg = 0;
#pragma unroll
        for (int q0 = 0; q0 < 5; q0++) {
            int q = j + 4 * q0;
            float4 x = row[q];
            int cc = 4 * q;
            if (x.x > m) { m = x.x; arg = cc; }
            if (x.y > m) { m = x.y; arg = cc + 1; }
            if (x.z > m) { m = x.z; arg = cc + 2; }
            if (x.w > m) { m = x.w; arg = cc + 3; }
        }
#pragma unroll
        for (int off = 1; off < 4; off <<= 1) {
            float mo = __shfl_xor_sync(0xffffffffu, m, off);
            int ao = __shfl_xor_sync(0xffffffffu, arg, off);
            if (mo > m || (mo == m && ao < arg)) { m = mo; arg = ao; }
        }
        if (j == 0) {
            sc[e] = __uint_as_float(kbits);
            lb[e] = arg;
            float4 an = reinterpret_cast<const float4*>(anchors)[a];
            float aw = an.z - an.x, ah = an.w - an.y;
            float acx = an.x + 0.5f * aw, acy = an.y + 0.5f * ah;
            float4 rg = reinterpret_cast<const float4*>(regs)[(size_t)b * A_N + a];
            float cx = acx + rg.x * aw;
            float cy = acy + rg.y * ah;
            float dw = fminf(fmaxf(rg.z, -4.0f), 4.0f);
            float dh = fminf(fmaxf(rg.w, -4.0f), 4.0f);
            float ww = aw * expf(dw);
            float hh = ah * expf(dh);
            float x1 = fminf(fmaxf(cx - 0.5f * ww, 0.0f), IMG);
            float y1 = fminf(fmaxf(cy - 0.5f * hh, 0.0f), IMG);
            float x2 = fminf(fmaxf(cx + 0.5f * ww, 0.0f), IMG);
            float y2 = fminf(fmaxf(cy + 0.5f * hh, 0.0f), IMG);
            bx[e] = make_float4(x1, y1, x2, y2);
        }
    }
    __syncthreads();

    // NMS masks: 4 threads per candidate, 64 columns each
    {
        int i = tid >> 2, q = tid & 3;
        float4 me = bx[i];
        float myarea = fmaxf(me.z - me.x, 0.0f) * fmaxf(me.w - me.y, 0.0f);
        unsigned w0 = 0u, w1 = 0u;
        int j0 = q * 64;
#pragma unroll 4
        for (int jj = 0; jj < 64; jj++) {
            float4 o = bx[j0 + jj];
            float ix1 = fmaxf(me.x, o.x);
            float iy1 = fmaxf(me.y, o.y);
            float ix2 = fminf(me.z, o.z);
            float iy2 = fminf(me.w, o.w);
            float iw = fmaxf(ix2 - ix1, 0.0f);
            float ih = fmaxf(iy2 - iy1, 0.0f);
            float inter = iw * ih;
            float oarea = fmaxf(o.z - o.x, 0.0f) * fmaxf(o.w - o.y, 0.0f);
            float uni = myarea + oarea - inter;
            float iou = inter / fmaxf(uni, 1e-8f);
            if (iou > 0.5f) {
                if (jj < 32) w0 |= 1u << jj;
                else w1 |= 1u << (jj - 32);
            }
        }
        msk[i * 8 + q * 2 + 0] = w0;
        msk[i * 8 + q * 2 + 1] = w1;
    }
    __syncthreads();

    // warp-cooperative sequential keep (lanes 0..7 own one word each)
    if (tid < 8) {
        unsigned keep_my = 0u;
        for (int i = 0; i < K_N; i++) {
            int wi = i >> 5;
            unsigned wm = (tid < wi) ? 0xFFFFFFFFu
                         : (tid == wi ? ((1u << (i & 31)) - 1u) : 0u);
            unsigned mm = msk[i * 8 + tid] & keep_my & wm;
            bool sup = __any_sync(0xFFu, mm != 0u);
            bool k0 = sc[i] > 0.0f;
            if (tid == wi && k0 && !sup) keep_my |= 1u << (i & 31);
        }
        keepw[tid] = keep_my;
    }
    __syncthreads();

    // output
    if (tid < K_N) {
        bool kp = (keepw[tid >> 5] >> (tid & 31)) & 1u;
        float kf = kp ? 1.0f : 0.0f;
        int base = b * K_N + tid;
        float4 me = bx[tid];
        out[base * 5 + 0] = me.x * kf;
        out[base * 5 + 1] = me.y * kf;
        out[base * 5 + 2] = me.z * kf;
        out[base * 5 + 3] = me.w * kf;
        out[base * 5 + 4] = sc[tid] * kf;
        if (out_size >= B_N * K_N * 5 + B_N * K_N)
            out[B_N * K_N * 5 + base] = (float)lb[tid];
        if (out_size >= B_N * K_N * 5 + 2 * B_N * K_N)
            out[B_N * K_N * 5 + B_N * K_N + base] = kf;
    }
}

// ============================================================
extern "C" void kernel_launch(void* const* d_in, const int* in_sizes, int n_in,
                              void* d_out, int out_size) {
    const float* cls = nullptr;
    const float* regs = nullptr;
    const float* anchors = nullptr;
    for (int i = 0; i < n_in; i++) {
        if (in_sizes[i] == B_N * A_N * C_N) cls = (const float*)d_in[i];
        else if (in_sizes[i] == B_N * A_N * 4) regs = (const float*)d_in[i];
        else if (in_sizes[i] == A_N * 4) anchors = (const float*)d_in[i];
    }
    if (!cls || !regs || !anchors) return;

    float* out = (float*)d_out;

    const int SMEM_K2 = 65536 + 4096 + 1024 + 1024 + 8192;
    cudaFuncSetAttribute(k_merge_nms, cudaFuncAttributeMaxDynamicSharedMemorySize, SMEM_K2);

    k_topk_local<<<B_N * NCH, 512>>>(cls);
    k_merge_nms<<<B_N, 1024, SMEM_K2>>>(cls, regs, anchors, out, out_size);
}

// round 6
// speedup vs baseline: 3.2708x; 1.1166x over previous
#include <cuda_runtime.h>
#include <math.h>
#include <stdint.h>

#define A_N 49104
#define B_N 8
#define C_N 80
#define K_N 256
#define IMG 512.0f
#define ROW4 20                 // 80 floats = 20 float4 per anchor
#define CH 2048                 // anchors per chunk
#define NCH 24                  // chunks per batch

typedef unsigned long long u64;

// -------- device scratch --------
__device__ u64 g_cand[B_N * NCH * K_N];   // chunk top-256 lists
__device__ u64 g_oct [B_N * 4 * K_N];     // octet top-256 lists

// ============================================================
// warp-level helpers for register bitonic sort (desc)
// ============================================================
__device__ __forceinline__ void cx_reg(u64& a, u64& b, bool desc) {
    u64 lo = (a < b) ? a : b;
    u64 hi = (a < b) ? b : a;
    a = desc ? hi : lo;
    b = desc ? lo : hi;
}
__device__ __forceinline__ u64 cx_shfl(u64 v, int j, bool desc, int lane) {
    u64 pv = __shfl_xor_sync(0xffffffffu, v, j);
    bool lower = (lane & j) == 0;
    bool keepmax = (desc == lower);
    u64 mx = (v > pv) ? v : pv;
    u64 mn = (v > pv) ? pv : v;
    return keepmax ? mx : mn;
}

// ============================================================
// K1: fused score + chunk top-256 (unchanged from R5).
// ============================================================
__global__ __launch_bounds__(512) void k_topk_local(const float* __restrict__ cls) {
    __shared__ u64 sk[CH];
    const int tid = threadIdx.x;
    const int lane = tid & 31;
    const int w = tid >> 5;
    const int b = blockIdx.x / NCH;
    const int c = blockIdx.x % NCH;
    const int base = c * CH;
    const float4* cls4 = reinterpret_cast<const float4*>(cls) + (size_t)b * A_N * ROW4;

#pragma unroll
    for (int it = 0; it < (CH * 4) / 512; it++) {
        int task = it * 512 + tid;
        int al = task >> 2;
        int j = task & 3;
        int a = base + al;
        float m = -INFINITY;
        if (a < A_N) {
            const float4* row = cls4 + (size_t)a * ROW4 + j;
#pragma unroll
            for (int i = 0; i < 5; i++) {
                float4 v = row[i * 4];
                m = fmaxf(m, fmaxf(fmaxf(v.x, v.y), fmaxf(v.z, v.w)));
            }
        }
        m = fmaxf(m, __shfl_xor_sync(0xffffffffu, m, 1));
        m = fmaxf(m, __shfl_xor_sync(0xffffffffu, m, 2));
        if (j == 0) {
            u64 key = 0ull;
            if (a < A_N) {
                float score = 1.0f / (1.0f + expf(-m));
                if (!(score > 0.01f)) score = 0.0f;
                key = ((u64)__float_as_uint(score) << 32) |
                      (u64)(0xFFFFFFFFu - (unsigned)a);
            }
            sk[al] = key;
        }
    }
    __syncthreads();

    u64 v[4];
#pragma unroll
    for (int r = 0; r < 4; r++) v[r] = sk[w * 128 + r * 32 + lane];

    for (int k = 2; k <= 128; k <<= 1) {
        for (int j = k >> 1; j >= 1; j >>= 1) {
            if (j >= 32) {
                int jr = j >> 5;
#pragma unroll
                for (int r = 0; r < 4; r++) {
                    if ((r & jr) == 0) {
                        bool desc = (((r * 32) & k) == 0);
                        cx_reg(v[r], v[r | jr], desc);
                    }
                }
            } else {
#pragma unroll
                for (int r = 0; r < 4; r++) {
                    bool desc = (k >= 32) ? (((r * 32) & k) == 0)
                                          : ((lane & k) == 0);
                    v[r] = cx_shfl(v[r], j, desc, lane);
                }
            }
        }
    }
#pragma unroll
    for (int r = 0; r < 4; r++) sk[w * 128 + r * 32 + lane] = v[r];
    __syncthreads();

    // full merge pairs of 128 -> 8 sorted lists of 256
    for (int t = tid; t < 1024; t += 512) {
        int p = t >> 7, i = t & 127;
        int e = p * 256 + i, f = p * 256 + 255 - i;
        u64 x = sk[e], y = sk[f];
        if (x < y) { sk[e] = y; sk[f] = x; }
    }
    __syncthreads();
    for (int j = 64; j >= 1; j >>= 1) {
        for (int t = tid; t < 1024; t += 512) {
            int p = t >> 7, i = t & 127;
            int e = p * 256 + (((i & ~(j - 1)) << 1) | (i & (j - 1)));
            int f = e + j;
            u64 x = sk[e], y = sk[f];
            if (x < y) { sk[e] = y; sk[f] = x; }
        }
        __syncthreads();
    }

    // truncating merges 8 -> 1
    for (int lvl = 0; lvl < 3; lvl++) {
        int npair = 4 >> lvl;
        int stride = 512 << lvl;
        for (int t = tid; t < npair * 256; t += 512) {
            int p = t >> 8, i = t & 255;
            int A = p * stride, B = A + (stride >> 1);
            u64 x = sk[A + i], y = sk[B + 255 - i];
            if (y > x) sk[A + i] = y;
        }
        __syncthreads();
        for (int j = 128; j >= 1; j >>= 1) {
            int ncmp = npair * 128;
            for (int t = tid; t < ncmp; t += 512) {
                int p = t >> 7, i = t & 127;
                int A = p * stride;
                int e = A + (((i & ~(j - 1)) << 1) | (i & (j - 1)));
                int f = e + j;
                u64 x = sk[e], y = sk[f];
                if (x < y) { sk[e] = y; sk[f] = x; }
            }
            __syncthreads();
        }
    }

    if (tid < K_N)
        g_cand[blockIdx.x * K_N + tid] = sk[tid];
}

// ============================================================
// K2a: merge 6 chunk-lists -> octet top-256. grid = B_N*4.
// ============================================================
__global__ __launch_bounds__(512) void k_merge8() {
    __shared__ u64 keys[2048];
    const int tid = threadIdx.x;
    const int b = blockIdx.x >> 2;
    const int o = blockIdx.x & 3;

    for (int i = tid; i < 2048; i += 512) {
        int l = i >> 8;
        keys[i] = (l < 6) ? g_cand[(b * NCH + o * 6 + l) * K_N + (i & 255)] : 0ull;
    }
    __syncthreads();

#pragma unroll
    for (int lvl = 0; lvl < 3; lvl++) {
        int npair = 4 >> lvl;
        for (int t = tid; t < npair * 256; t += 512) {
            int p = t >> 8, i = t & 255;
            int A = p * (512 << lvl), B = A + (256 << lvl);
            u64 x = keys[A + i], y = keys[B + 255 - i];
            if (y > x) keys[A + i] = y;
        }
        __syncthreads();
        for (int j = 128; j >= 1; j >>= 1) {
            for (int t = tid; t < npair * 128; t += 512) {
                int p = t >> 7, i = t & 127;
                int seg = p * (512 << lvl);
                int e = seg + (((i & ~(j - 1)) << 1) | (i & (j - 1)));
                int f = e + j;
                u64 x = keys[e], y = keys[f];
                if (x < y) { keys[e] = y; keys[f] = x; }
            }
            __syncthreads();
        }
    }

    if (tid < K_N)
        g_oct[blockIdx.x * K_N + tid] = keys[tid];
}

// ============================================================
// K2b: merge 4 octet lists + gather/decode + NMS (Jacobi) + output.
// ============================================================
__global__ __launch_bounds__(1024) void k_final(const float* __restrict__ cls,
                                                const float* __restrict__ regs,
                                                const float* __restrict__ anchors,
                                                float* __restrict__ out,
                                                int out_size) {
    const int b = blockIdx.x;
    const int tid = threadIdx.x;

    __shared__ u64 keys[1024];
    __shared__ float4 bx[K_N];
    __shared__ float sc[K_N];
    __shared__ int lb[K_N];
    __shared__ unsigned msk[K_N][8];
    __shared__ unsigned keepw[8];
    __shared__ int changed;

    if (tid < 1024) keys[tid] = g_oct[b * 4 * K_N + tid];
    __syncthreads();

    // 2 truncating merge levels: 4 lists -> 1
#pragma unroll
    for (int lvl = 0; lvl < 2; lvl++) {
        int npair = 2 >> lvl;
        for (int t = tid; t < npair * 256; t += 1024) {
            int p = t >> 8, i = t & 255;
            int A = p * (512 << lvl), B = A + (256 << lvl);
            u64 x = keys[A + i], y = keys[B + 255 - i];
            if (y > x) keys[A + i] = y;
        }
        __syncthreads();
        for (int j = 128; j >= 1; j >>= 1) {
            for (int t = tid; t < npair * 128; t += 1024) {
                int p = t >> 7, i = t & 127;
                int seg = p * (512 << lvl);
                int e = seg + (((i & ~(j - 1)) << 1) | (i & (j - 1)));
                int f = e + j;
                u64 x = keys[e], y = keys[f];
                if (x < y) { keys[e] = y; keys[f] = x; }
            }
            __syncthreads();
        }
    }

    // gather: 4 threads per winner recompute argmax; j==0 decodes box
    {
        int e = tid >> 2, j = tid & 3;
        u64 v = keys[e];
        unsigned kbits = (unsigned)(v >> 32);
        unsigned a = 0xFFFFFFFFu - (unsigned)(v & 0xFFFFFFFFu);
        const float4* row = reinterpret_cast<const float4*>(cls) +
                            ((size_t)b * A_N + a) * ROW4;
        float m = -INFINITY;
        int arg = 0;
#pragma unroll
        for (int q0 = 0; q0 < 5; q0++) {
            int q = j + 4 * q0;
            float4 x = row[q];
            int cc = 4 * q;
            if (x.x > m) { m = x.x; arg = cc; }
            if (x.y > m) { m = x.y; arg = cc + 1; }
            if (x.z > m) { m = x.z; arg = cc + 2; }
            if (x.w > m) { m = x.w; arg = cc + 3; }
        }
#pragma unroll
        for (int off = 1; off < 4; off <<= 1) {
            float mo = __shfl_xor_sync(0xffffffffu, m, off);
            int ao = __shfl_xor_sync(0xffffffffu, arg, off);
            if (mo > m || (mo == m && ao < arg)) { m = mo; arg = ao; }
        }
        if (j == 0) {
            sc[e] = __uint_as_float(kbits);
            lb[e] = arg;
            float4 an = reinterpret_cast<const float4*>(anchors)[a];
            float aw = an.z - an.x, ah = an.w - an.y;
            float acx = an.x + 0.5f * aw, acy = an.y + 0.5f * ah;
            float4 rg = reinterpret_cast<const float4*>(regs)[(size_t)b * A_N + a];
            float cx = acx + rg.x * aw;
            float cy = acy + rg.y * ah;
            float dw = fminf(fmaxf(rg.z, -4.0f), 4.0f);
            float dh = fminf(fmaxf(rg.w, -4.0f), 4.0f);
            float ww = aw * expf(dw);
            float hh = ah * expf(dh);
            float x1 = fminf(fmaxf(cx - 0.5f * ww, 0.0f), IMG);
            float y1 = fminf(fmaxf(cy - 0.5f * hh, 0.0f), IMG);
            float x2 = fminf(fmaxf(cx + 0.5f * ww, 0.0f), IMG);
            float y2 = fminf(fmaxf(cy + 0.5f * hh, 0.0f), IMG);
            bx[e] = make_float4(x1, y1, x2, y2);
        }
    }
    __syncthreads();

    // NMS masks: 4 threads per candidate, 64 columns each
    {
        int i = tid >> 2, q = tid & 3;
        float4 me = bx[i];
        float myarea = fmaxf(me.z - me.x, 0.0f) * fmaxf(me.w - me.y, 0.0f);
        unsigned w0 = 0u, w1 = 0u;
        int j0 = q * 64;
#pragma unroll 4
        for (int jj = 0; jj < 64; jj++) {
            float4 o = bx[j0 + jj];
            float ix1 = fmaxf(me.x, o.x);
            float iy1 = fmaxf(me.y, o.y);
            float ix2 = fminf(me.z, o.z);
            float iy2 = fminf(me.w, o.w);
            float iw = fmaxf(ix2 - ix1, 0.0f);
            float ih = fmaxf(iy2 - iy1, 0.0f);
            float inter = iw * ih;
            float oarea = fmaxf(o.z - o.x, 0.0f) * fmaxf(o.w - o.y, 0.0f);
            float uni = myarea + oarea - inter;
            float iou = inter / fmaxf(uni, 1e-8f);
            if (iou > 0.5f) {
                if (jj < 32) w0 |= 1u << jj;
                else w1 |= 1u << (jj - 32);
            }
        }
        msk[i][q * 2 + 0] = w0;
        msk[i][q * 2 + 1] = w1;
    }
    __syncthreads();

    // Jacobi fixpoint NMS keep: keep_i = ok_i & !any_{j<i}(keep_j & M_ij).
    // Unique fixpoint == sequential NMS result; converges <= 256 iters.
    bool ok = false;
    unsigned mw[8];
    int wi = tid >> 5;
    unsigned below = (1u << (tid & 31)) - 1u;
    if (tid < K_N) {
        ok = sc[tid] > 0.0f;
#pragma unroll
        for (int w = 0; w < 8; w++) mw[w] = msk[tid][w];
        unsigned word = __ballot_sync(0xffffffffu, ok);
        if ((tid & 31) == 0) keepw[wi] = word;
    }
    __syncthreads();

    for (int iter = 0; iter < K_N; iter++) {
        bool newbit = false;
        unsigned oldword = 0u;
        if (tid < K_N) {
            oldword = keepw[wi];
            unsigned sup = 0u;
#pragma unroll
            for (int w = 0; w < 8; w++) {
                unsigned kw = keepw[w];
                unsigned lim = (w < wi) ? 0xFFFFFFFFu : (w == wi ? below : 0u);
                sup |= mw[w] & kw & lim;
            }
            newbit = ok && (sup == 0u);
        }
        __syncthreads();
        if (tid == 512) changed = 0;
        __syncthreads();
        if (tid < K_N) {
            unsigned word = __ballot_sync(0xffffffffu, newbit);
            if ((tid & 31) == 0) {
                if (word != oldword) changed = 1;
                keepw[wi] = word;
            }
        }
        __syncthreads();
        if (!changed) break;
    }

    // output
    if (tid < K_N) {
        bool kp = (keepw[wi] >> (tid & 31)) & 1u;
        float kf = kp ? 1.0f : 0.0f;
        int base = b * K_N + tid;
        float4 me = bx[tid];
        out[base * 5 + 0] = me.x * kf;
        out[base * 5 + 1] = me.y * kf;
        out[base * 5 + 2] = me.z * kf;
        out[base * 5 + 3] = me.w * kf;
        out[base * 5 + 4] = sc[tid] * kf;
        if (out_size >= B_N * K_N * 5 + B_N * K_N)
            out[B_N * K_N * 5 + base] = (float)lb[tid];
        if (out_size >= B_N * K_N * 5 + 2 * B_N * K_N)
            out[B_N * K_N * 5 + B_N * K_N + base] = kf;
    }
}

// ============================================================
extern "C" void kernel_launch(void* const* d_in, const int* in_sizes, int n_in,
                              void* d_out, int out_size) {
    const float* cls = nullptr;
    const float* regs = nullptr;
    const float* anchors = nullptr;
    for (int i = 0; i < n_in; i++) {
        if (in_sizes[i] == B_N * A_N * C_N) cls = (const float*)d_in[i];
        else if (in_sizes[i] == B_N * A_N * 4) regs = (const float*)d_in[i];
        else if (in_sizes[i] == A_N * 4) anchors = (const float*)d_in[i];
    }
    if (!cls || !regs || !anchors) return;

    float* out = (float*)d_out;

    k_topk_local<<<B_N * NCH, 512>>>(cls);
    k_merge8<<<B_N * 4, 512>>>();
    k_final<<<B_N, 1024>>>(cls, regs, anchors, out, out_size);
}

// round 7
// speedup vs baseline: 3.4135x; 1.0436x over previous
#include <cuda_runtime.h>
#include <math.h>
#include <stdint.h>

#define A_N 49104
#define B_N 8
#define C_N 80
#define K_N 256
#define IMG 512.0f
#define ROW4 20                 // 80 floats = 20 float4 per anchor
#define CH 1024                 // anchors per chunk
#define NCH 48                  // chunks per batch (48*1024 >= 49104)

typedef unsigned long long u64;

// -------- device scratch --------
__device__ u64 g_cand[B_N * NCH * K_N];   // chunk top-256 lists
__device__ u64 g_oct [B_N * 8 * K_N];     // octet top-256 lists

// ============================================================
// warp-level helpers for register bitonic sort (desc)
// ============================================================
__device__ __forceinline__ void cx_reg(u64& a, u64& b, bool desc) {
    u64 lo = (a < b) ? a : b;
    u64 hi = (a < b) ? b : a;
    a = desc ? hi : lo;
    b = desc ? lo : hi;
}
__device__ __forceinline__ u64 cx_shfl(u64 v, int j, bool desc, int lane) {
    u64 pv = __shfl_xor_sync(0xffffffffu, v, j);
    bool lower = (lane & j) == 0;
    bool keepmax = (desc == lower);
    u64 mx = (v > pv) ? v : pv;
    u64 mn = (v > pv) ? pv : v;
    return keepmax ? mx : mn;
}

// ============================================================
// K1: fused score + chunk top-256.  CH=1024, 256 threads.
// ============================================================
__global__ __launch_bounds__(256) void k_topk_local(const float* __restrict__ cls) {
    __shared__ u64 sk[CH];
    const int tid = threadIdx.x;
    const int lane = tid & 31;
    const int w = tid >> 5;                 // warp 0..7
    const int b = blockIdx.x / NCH;
    const int c = blockIdx.x % NCH;
    const int base = c * CH;
    const float4* cls4 = reinterpret_cast<const float4*>(cls) + (size_t)b * A_N * ROW4;

    // ---- scores: 4 threads per anchor ----
#pragma unroll
    for (int it = 0; it < (CH * 4) / 256; it++) {
        int task = it * 256 + tid;
        int al = task >> 2;
        int j = task & 3;
        int a = base + al;
        float m = -INFINITY;
        if (a < A_N) {
            const float4* row = cls4 + (size_t)a * ROW4 + j;
#pragma unroll
            for (int i = 0; i < 5; i++) {
                float4 v = row[i * 4];
                m = fmaxf(m, fmaxf(fmaxf(v.x, v.y), fmaxf(v.z, v.w)));
            }
        }
        m = fmaxf(m, __shfl_xor_sync(0xffffffffu, m, 1));
        m = fmaxf(m, __shfl_xor_sync(0xffffffffu, m, 2));
        if (j == 0) {
            u64 key = 0ull;
            if (a < A_N) {
                float score = 1.0f / (1.0f + expf(-m));
                if (!(score > 0.01f)) score = 0.0f;
                key = ((u64)__float_as_uint(score) << 32) |
                      (u64)(0xFFFFFFFFu - (unsigned)a);
            }
            sk[al] = key;
        }
    }
    __syncthreads();

    // ---- register bitonic sort: each warp sorts 128 keys desc ----
    u64 v[4];
#pragma unroll
    for (int r = 0; r < 4; r++) v[r] = sk[w * 128 + r * 32 + lane];

    for (int k = 2; k <= 128; k <<= 1) {
        for (int j = k >> 1; j >= 1; j >>= 1) {
            if (j >= 32) {
                int jr = j >> 5;
#pragma unroll
                for (int r = 0; r < 4; r++) {
                    if ((r & jr) == 0) {
                        bool desc = (((r * 32) & k) == 0);
                        cx_reg(v[r], v[r | jr], desc);
                    }
                }
            } else {
#pragma unroll
                for (int r = 0; r < 4; r++) {
                    bool desc = (k >= 32) ? (((r * 32) & k) == 0)
                                          : ((lane & k) == 0);
                    v[r] = cx_shfl(v[r], j, desc, lane);
                }
            }
        }
    }
#pragma unroll
    for (int r = 0; r < 4; r++) sk[w * 128 + r * 32 + lane] = v[r];
    __syncthreads();

    // ---- L1: full merge pairs of 128 -> 4 sorted lists of 256 ----
    for (int t = tid; t < 512; t += 256) {
        int p = t >> 7, i = t & 127;
        int e = p * 256 + i, f = p * 256 + 255 - i;
        u64 x = sk[e], y = sk[f];
        if (x < y) { sk[e] = y; sk[f] = x; }
    }
    __syncthreads();
    for (int j = 64; j >= 1; j >>= 1) {
        for (int t = tid; t < 512; t += 256) {
            int p = t >> 7, i = t & 127;
            int e = p * 256 + (((i & ~(j - 1)) << 1) | (i & (j - 1)));
            int f = e + j;
            u64 x = sk[e], y = sk[f];
            if (x < y) { sk[e] = y; sk[f] = x; }
        }
        __syncthreads();
    }

    // ---- truncating merges 4 -> 1 (2 levels) ----
    for (int lvl = 0; lvl < 2; lvl++) {
        int npair = 2 >> lvl;               // 2, 1
        int stride = 512 << lvl;
        for (int t = tid; t < npair * 256; t += 256) {
            int p = t >> 8, i = t & 255;
            int A = p * stride, B = A + (stride >> 1);
            u64 x = sk[A + i], y = sk[B + 255 - i];
            if (y > x) sk[A + i] = y;
        }
        __syncthreads();
        for (int j = 128; j >= 1; j >>= 1) {
            int ncmp = npair * 128;
            for (int t = tid; t < ncmp; t += 256) {
                int p = t >> 7, i = t & 127;
                int A = p * stride;
                int e = A + (((i & ~(j - 1)) << 1) | (i & (j - 1)));
                int f = e + j;
                u64 x = sk[e], y = sk[f];
                if (x < y) { sk[e] = y; sk[f] = x; }
            }
            __syncthreads();
        }
    }

    if (tid < K_N)
        g_cand[blockIdx.x * K_N + tid] = sk[tid];
}

// ============================================================
// K2a: merge 6 chunk-lists -> one top-256. grid = B_N*8.
// ============================================================
__global__ __launch_bounds__(512) void k_merge() {
    __shared__ u64 keys[2048];
    const int tid = threadIdx.x;
    const int b = blockIdx.x >> 3;
    const int o = blockIdx.x & 7;

    for (int i = tid; i < 2048; i += 512) {
        int l = i >> 8;
        keys[i] = (l < 6) ? g_cand[(b * NCH + o * 6 + l) * K_N + (i & 255)] : 0ull;
    }
    __syncthreads();

#pragma unroll
    for (int lvl = 0; lvl < 3; lvl++) {
        int npair = 4 >> lvl;
        for (int t = tid; t < npair * 256; t += 512) {
            int p = t >> 8, i = t & 255;
            int A = p * (512 << lvl), B = A + (256 << lvl);
            u64 x = keys[A + i], y = keys[B + 255 - i];
            if (y > x) keys[A + i] = y;
        }
        __syncthreads();
        for (int j = 128; j >= 1; j >>= 1) {
            for (int t = tid; t < npair * 128; t += 512) {
                int p = t >> 7, i = t & 127;
                int seg = p * (512 << lvl);
                int e = seg + (((i & ~(j - 1)) << 1) | (i & (j - 1)));
                int f = e + j;
                u64 x = keys[e], y = keys[f];
                if (x < y) { keys[e] = y; keys[f] = x; }
            }
            __syncthreads();
        }
    }

    if (tid < K_N)
        g_oct[blockIdx.x * K_N + tid] = keys[tid];
}

// ============================================================
// K2b: merge 8 octet lists + gather/decode + NMS (Jacobi) + output.
// ============================================================
__global__ __launch_bounds__(1024) void k_final(const float* __restrict__ cls,
                                                const float* __restrict__ regs,
                                                const float* __restrict__ anchors,
                                                float* __restrict__ out,
                                                int out_size) {
    const int b = blockIdx.x;
    const int tid = threadIdx.x;

    __shared__ u64 keys[2048];
    __shared__ float4 bx[K_N];
    __shared__ float sc[K_N];
    __shared__ int lb[K_N];
    __shared__ unsigned msk[K_N][8];
    __shared__ unsigned keepw[8];
    __shared__ int changed;

    for (int i = tid; i < 2048; i += 1024)
        keys[i] = g_oct[b * 8 * K_N + i];
    __syncthreads();

    // 3 truncating merge levels: 8 lists -> 1
#pragma unroll
    for (int lvl = 0; lvl < 3; lvl++) {
        int npair = 4 >> lvl;
        for (int t = tid; t < npair * 256; t += 1024) {
            int p = t >> 8, i = t & 255;
            int A = p * (512 << lvl), B = A + (256 << lvl);
            u64 x = keys[A + i], y = keys[B + 255 - i];
            if (y > x) keys[A + i] = y;
        }
        __syncthreads();
        for (int j = 128; j >= 1; j >>= 1) {
            for (int t = tid; t < npair * 128; t += 1024) {
                int p = t >> 7, i = t & 127;
                int seg = p * (512 << lvl);
                int e = seg + (((i & ~(j - 1)) << 1) | (i & (j - 1)));
                int f = e + j;
                u64 x = keys[e], y = keys[f];
                if (x < y) { keys[e] = y; keys[f] = x; }
            }
            __syncthreads();
        }
    }

    // gather: 4 threads per winner recompute argmax; j==0 decodes box
    {
        int e = tid >> 2, j = tid & 3;
        u64 v = keys[e];
        unsigned kbits = (unsigned)(v >> 32);
        unsigned a = 0xFFFFFFFFu - (unsigned)(v & 0xFFFFFFFFu);
        const float4* row = reinterpret_cast<const float4*>(cls) +
                            ((size_t)b * A_N + a) * ROW4;
        float m = -INFINITY;
        int arg = 0;
#pragma unroll
        for (int q0 = 0; q0 < 5; q0++) {
            int q = j + 4 * q0;
            float4 x = row[q];
            int cc = 4 * q;
            if (x.x > m) { m = x.x; arg = cc; }
            if (x.y > m) { m = x.y; arg = cc + 1; }
            if (x.z > m) { m = x.z; arg = cc + 2; }
            if (x.w > m) { m = x.w; arg = cc + 3; }
        }
#pragma unroll
        for (int off = 1; off < 4; off <<= 1) {
            float mo = __shfl_xor_sync(0xffffffffu, m, off);
            int ao = __shfl_xor_sync(0xffffffffu, arg, off);
            if (mo > m || (mo == m && ao < arg)) { m = mo; arg = ao; }
        }
        if (j == 0) {
            sc[e] = __uint_as_float(kbits);
            lb[e] = arg;
            float4 an = reinterpret_cast<const float4*>(anchors)[a];
            float aw = an.z - an.x, ah = an.w - an.y;
            float acx = an.x + 0.5f * aw, acy = an.y + 0.5f * ah;
            float4 rg = reinterpret_cast<const float4*>(regs)[(size_t)b * A_N + a];
            float cx = acx + rg.x * aw;
            float cy = acy + rg.y * ah;
            float dw = fminf(fmaxf(rg.z, -4.0f), 4.0f);
            float dh = fminf(fmaxf(rg.w, -4.0f), 4.0f);
            float ww = aw * expf(dw);
            float hh = ah * expf(dh);
            float x1 = fminf(fmaxf(cx - 0.5f * ww, 0.0f), IMG);
            float y1 = fminf(fmaxf(cy - 0.5f * hh, 0.0f), IMG);
            float x2 = fminf(fmaxf(cx + 0.5f * ww, 0.0f), IMG);
            float y2 = fminf(fmaxf(cy + 0.5f * hh, 0.0f), IMG);
            bx[e] = make_float4(x1, y1, x2, y2);
        }
    }
    __syncthreads();

    // NMS masks: 4 threads per candidate, 64 columns each
    {
        int i = tid >> 2, q = tid & 3;
        float4 me = bx[i];
        float myarea = fmaxf(me.z - me.x, 0.0f) * fmaxf(me.w - me.y, 0.0f);
        unsigned w0 = 0u, w1 = 0u;
        int j0 = q * 64;
#pragma unroll 4
        for (int jj = 0; jj < 64; jj++) {
            float4 o = bx[j0 + jj];
            float ix1 = fmaxf(me.x, o.x);
            float iy1 = fmaxf(me.y, o.y);
            float ix2 = fminf(me.z, o.z);
            float iy2 = fminf(me.w, o.w);
            float iw = fmaxf(ix2 - ix1, 0.0f);
            float ih = fmaxf(iy2 - iy1, 0.0f);
            float inter = iw * ih;
            float oarea = fmaxf(o.z - o.x, 0.0f) * fmaxf(o.w - o.y, 0.0f);
            float uni = myarea + oarea - inter;
            float iou = inter / fmaxf(uni, 1e-8f);
            if (iou > 0.5f) {
                if (jj < 32) w0 |= 1u << jj;
                else w1 |= 1u << (jj - 32);
            }
        }
        msk[i][q * 2 + 0] = w0;
        msk[i][q * 2 + 1] = w1;
    }
    __syncthreads();

    // Jacobi fixpoint NMS keep (== sequential NMS result)
    bool ok = false;
    unsigned mw[8];
    int wi = tid >> 5;
    unsigned below = (1u << (tid & 31)) - 1u;
    if (tid < K_N) {
        ok = sc[tid] > 0.0f;
#pragma unroll
        for (int w = 0; w < 8; w++) mw[w] = msk[tid][w];
        unsigned word = __ballot_sync(0xffffffffu, ok);
        if ((tid & 31) == 0) keepw[wi] = word;
    }
    __syncthreads();

    for (int iter = 0; iter < K_N; iter++) {
        bool newbit = false;
        unsigned oldword = 0u;
        if (tid < K_N) {
            oldword = keepw[wi];
            unsigned sup = 0u;
#pragma unroll
            for (int w = 0; w < 8; w++) {
                unsigned kw = keepw[w];
                unsigned lim = (w < wi) ? 0xFFFFFFFFu : (w == wi ? below : 0u);
                sup |= mw[w] & kw & lim;
            }
            newbit = ok && (sup == 0u);
        }
        __syncthreads();
        if (tid == 512) changed = 0;
        __syncthreads();
        if (tid < K_N) {
            unsigned word = __ballot_sync(0xffffffffu, newbit);
            if ((tid & 31) == 0) {
                if (word != oldword) changed = 1;
                keepw[wi] = word;
            }
        }
        __syncthreads();
        if (!changed) break;
    }

    // output
    if (tid < K_N) {
        bool kp = (keepw[wi] >> (tid & 31)) & 1u;
        float kf = kp ? 1.0f : 0.0f;
        int base = b * K_N + tid;
        float4 me = bx[tid];
        out[base * 5 + 0] = me.x * kf;
        out[base * 5 + 1] = me.y * kf;
        out[base * 5 + 2] = me.z * kf;
        out[base * 5 + 3] = me.w * kf;
        out[base * 5 + 4] = sc[tid] * kf;
        if (out_size >= B_N * K_N * 5 + B_N * K_N)
            out[B_N * K_N * 5 + base] = (float)lb[tid];
        if (out_size >= B_N * K_N * 5 + 2 * B_N * K_N)
            out[B_N * K_N * 5 + B_N * K_N + base] = kf;
    }
}

// ============================================================
extern "C" void kernel_launch(void* const* d_in, const int* in_sizes, int n_in,
                              void* d_out, int out_size) {
    const float* cls = nullptr;
    const float* regs = nullptr;
    const float* anchors = nullptr;
    for (int i = 0; i < n_in; i++) {
        if (in_sizes[i] == B_N * A_N * C_N) cls = (const float*)d_in[i];
        else if (in_sizes[i] == B_N * A_N * 4) regs = (const float*)d_in[i];
        else if (in_sizes[i] == A_N * 4) anchors = (const float*)d_in[i];
    }
    if (!cls || !regs || !anchors) return;

    float* out = (float*)d_out;

    k_topk_local<<<B_N * NCH, 256>>>(cls);
    k_merge<<<B_N * 8, 512>>>();
    k_final<<<B_N, 1024>>>(cls, regs, anchors, out, out_size);
}